// round 11
// baseline (speedup 1.0000x reference)
#include <cuda_runtime.h>
#include <cuda_bf16.h>
#include <cstdint>

// Backlash scan, B=4096, T=2048. Warp-autonomous fused kernel, exact result:
//  - each warp owns 2 sequences (32 streams = 2 seq x 16 chunks), double-buffered
//    cp.async pipeline per warp; no __syncthreads anywhere
//  - 8-step speculative warm-up (merge prob per-step ~0.8 => ~3e-6 fail/chunk),
//    8 steps/stage, 17 stages; chunk-0 warm loads skipped entirely
//  - evict-first output stores; warp-local shfl validation + replay backstop

#define BB 4096
#define TT 2048
#define CHUNKS 16
#define LCH 128
#define SS 8
#define WARMS 1
#define WARM (WARMS * SS)       // 8
#define NST (WARMS + LCH / SS)  // 17
#define TPB 128
#define NW (TPB / 32)
#define STR 11                  // float4/stream/stage: 8 w + 2 x + 1 pad
#define NBUF 2

// One backlash step, bit-identical to the reference fp32 expression.
// h-thresholds via sign tests (exact for nonzero m).
__device__ __forceinline__ float bl_step(float prev, float xt, float4 wv) {
    float m_lo = wv.x, m_up = wv.y, c_lo = wv.z, c_up = wv.w;
    float a  = __fmul_rn(m_lo, xt);
    float bq = __fmul_rn(m_lo, c_lo);
    float cc = __fmul_rn(m_up, xt);
    float d  = __fmul_rn(m_up, c_up);
    float A1 = __fsub_rn(__fadd_rn(a, bq), prev);
    float A2 = __fsub_rn(__fsub_rn(prev, cc), d);
    bool p1 = ((A1 > 0.0f) && (m_lo > 0.0f)) || ((A1 < 0.0f) && (m_lo < 0.0f));
    bool p2 = ((A2 > 0.0f) && (m_up > 0.0f)) || ((A2 < 0.0f) && (m_up < 0.0f));
    float t1 = p1 ? 0.0f : a;
    float t2 = p1 ? 0.0f : bq;
    float t3 = p2 ? 0.0f : cc;
    float t4 = p2 ? 0.0f : d;
    float t5 = (p1 && p2) ? prev : 0.0f;
    return __fadd_rn(__fadd_rn(__fadd_rn(__fadd_rn(t1, t2), t3), t4), t5);
}

__device__ __forceinline__ void cp16(uint32_t dst, const float4* src) {
    asm volatile("cp.async.cg.shared.global [%0], [%1], 16;" :: "r"(dst), "l"(src));
}

__device__ __forceinline__ void stcs16(float4* p, float4 v) {
    asm volatile("st.global.cs.v4.f32 [%0], {%1, %2, %3, %4};"
                 :: "l"(p), "f"(v.x), "f"(v.y), "f"(v.z), "f"(v.w) : "memory");
}

// Warp-scope coalesced cp.async copies for stage s (5 KB: 32 streams).
// Chunk-0 warm loads (tb < 0) are skipped: their compute is discarded anyway.
__device__ __forceinline__ void issue_stage_w(const float* __restrict__ x,
                                              const float* __restrict__ w,
                                              int seq0, int s, uint32_t sb32, int lane) {
    // w: 8 passes x (4 streams x 8 lanes -> 4 full 128B segments / instr)
    #pragma unroll
    for (int p = 0; p < 8; p++) {
        int st = p * 4 + (lane >> 3);
        int j  = lane & 7;
        int sb = seq0 + (st >> 4);
        int sc = st & 15;
        int tb = sc * LCH - WARM + s * SS;
        if (tb >= 0)
            cp16(sb32 + (uint32_t)(st * STR + j) * 16,
                 (const float4*)w + (size_t)sb * TT + tb + j);
    }
    // x: 2 passes x (16 streams x lane-pairs -> full 32B sectors)
    #pragma unroll
    for (int p = 0; p < 2; p++) {
        int st = p * 16 + (lane >> 1);
        int k  = lane & 1;
        int sb = seq0 + (st >> 4);
        int sc = st & 15;
        int tb = sc * LCH - WARM + s * SS;
        if (tb >= 0)
            cp16(sb32 + (uint32_t)(st * STR + 8 + k) * 16,
                 (const float4*)(x + (size_t)sb * TT + tb) + k);
    }
    asm volatile("cp.async.commit_group;");
}

__global__ __launch_bounds__(TPB)
void backlash_fused(const float* __restrict__ x,
                    const float* __restrict__ w,
                    const float* __restrict__ out_prev,
                    float* __restrict__ out) {
    __shared__ float4 sB[NW][NBUF][32 * STR];   // 45056 B

    const int tid  = threadIdx.x;
    const int lane = tid & 31;
    const int wrp  = tid >> 5;
    const int seq0 = blockIdx.x * (2 * NW) + wrp * 2;   // 2 sequences per warp
    const int my_b = seq0 + (lane >> 4);
    const int my_c = lane & 15;

    const uint32_t b0 = (uint32_t)__cvta_generic_to_shared(&sB[wrp][0][0]);
    const uint32_t b1 = (uint32_t)__cvta_generic_to_shared(&sB[wrp][1][0]);

    const float op = (my_c == 0) ? out_prev[my_b] : 0.0f;
    float prev = 0.0f;
    float G = 0.0f;                 // state entering my chunk (post warm-up)

    issue_stage_w(x, w, seq0, 0, b0, lane);
    issue_stage_w(x, w, seq0, 1, b1, lane);

    #pragma unroll 1
    for (int s = 0; s < NST; s++) {
        if (s == NST - 1) { asm volatile("cp.async.wait_group 0;"); }
        else              { asm volatile("cp.async.wait_group 1;"); }
        __syncwarp();

        const uint32_t cb = (s & 1) ? b1 : b0;
        const float4* bp = &sB[wrp][s & 1][lane * STR];
        float4 x0 = bp[8];
        float4 x1 = bp[9];
        float o0, o1, o2, o3, o4, o5, o6, o7;
        prev = bl_step(prev, x0.x, bp[0]); o0 = prev;
        prev = bl_step(prev, x0.y, bp[1]); o1 = prev;
        prev = bl_step(prev, x0.z, bp[2]); o2 = prev;
        prev = bl_step(prev, x0.w, bp[3]); o3 = prev;
        prev = bl_step(prev, x1.x, bp[4]); o4 = prev;
        prev = bl_step(prev, x1.y, bp[5]); o5 = prev;
        prev = bl_step(prev, x1.z, bp[6]); o6 = prev;
        prev = bl_step(prev, x1.w, bp[7]); o7 = prev;

        const bool emit = (s >= WARMS);
        if (emit) {
            // outputs into the consumed x slots (conflict-free STS.128)
            float4* wp = &sB[wrp][s & 1][lane * STR];
            wp[8] = make_float4(o0, o1, o2, o3);
            wp[9] = make_float4(o4, o5, o6, o7);
        }
        if (s == WARMS - 1) {               // warm-up complete
            if (my_c == 0) prev = op;       // chunk 0: discard garbage, use true init
            G = prev;
        }
        __syncwarp();

        if (emit) {
            // coalesced float4 stores (lane pairs; full 32B sectors), evict-first
            #pragma unroll
            for (int p = 0; p < 2; p++) {
                int st = p * 16 + (lane >> 1);
                int k  = lane & 1;
                int sb = seq0 + (st >> 4);
                int sc = st & 15;
                float4 v = sB[wrp][s & 1][st * STR + 8 + k];
                stcs16(((float4*)out) + (size_t)sb * (TT / 4) + sc * (LCH / 4)
                                      + (s - WARMS) * (SS / 4) + k, v);
            }
        }
        if (s + 2 < NST) {
            // Cross-lane reads above must complete before refilling this buffer.
            __syncwarp();
            issue_stage_w(x, w, seq0, s + 2, cb, lane);   // (s+2)&1 == s&1
        }
    }

    // ---- warp-local validation + replay backstop (exactness guarantee) ----
    const unsigned full = 0xFFFFFFFFu;
    float E = prev;
    float Ep = __shfl_up_sync(full, E, 1);
    bool ok = (my_c == 0) || (Ep == G);
    if (__ballot_sync(full, ok) != full) {
        // Rare: speculative warm-up failed to merge somewhere in this warp.
        int base = lane & 16;
        float st = E;                       // valid on owner lanes (my_c==0)
        #pragma unroll 1
        for (int c = 1; c < CHUNKS; c++) {
            float g = __shfl_sync(full, G, base + c);
            float e = __shfl_sync(full, E, base + c);
            if (my_c == 0) {
                if (st == g) {
                    st = e;
                } else {
                    const float*  xb = x + (size_t)my_b * TT;
                    const float4* wb = (const float4*)w + (size_t)my_b * TT;
                    float*        ob = out + (size_t)my_b * TT;
                    for (int t = c * LCH; t < (c + 1) * LCH; t++) {
                        st = bl_step(st, xb[t], wb[t]);
                        ob[t] = st;
                    }
                }
            }
        }
    }
}

extern "C" void kernel_launch(void* const* d_in, const int* in_sizes, int n_in,
                              void* d_out, int out_size) {
    const float* x = nullptr;        // (B, T, 1)
    const float* out_prev = nullptr; // (B, 1, 1)
    const float* w = nullptr;        // (B, T, 4)
    for (int i = 0; i < n_in; i++) {
        if (in_sizes[i] == BB * TT)          x = (const float*)d_in[i];
        else if (in_sizes[i] == BB)          out_prev = (const float*)d_in[i];
        else if (in_sizes[i] == BB * TT * 4) w = (const float*)d_in[i];
    }
    float* out = (float*)d_out;

    backlash_fused<<<BB / (2 * NW), TPB>>>(x, w, out_prev, out);
}

// round 12
// speedup vs baseline: 1.3438x; 1.3438x over previous
#include <cuda_runtime.h>
#include <cuda_bf16.h>
#include <cstdint>

// Backlash scan, B=4096, T=2048. Warp-autonomous fused kernel, exact result:
//  - each warp owns 2 sequences (32 streams = 2 seq x 16 chunks), double-buffered
//    cp.async pipeline per warp; no __syncthreads anywhere
//  - 16-step speculative warm-up (validated operating point), 8 steps/stage,
//    18 stages; chunk-0 out-of-range warm loads skipped (predicated, not clamped)
//  - evict-first output stores; warp-local shfl validation + replay backstop

#define BB 4096
#define TT 2048
#define CHUNKS 16
#define LCH 128
#define SS 8
#define WARMS 2
#define WARM (WARMS * SS)       // 16
#define NST (WARMS + LCH / SS)  // 18
#define TPB 128
#define NW (TPB / 32)
#define STR 11                  // float4/stream/stage: 8 w + 2 x + 1 pad
#define NBUF 2

// One backlash step, bit-identical to the reference fp32 expression.
// h-thresholds via sign tests (exact for nonzero m).
__device__ __forceinline__ float bl_step(float prev, float xt, float4 wv) {
    float m_lo = wv.x, m_up = wv.y, c_lo = wv.z, c_up = wv.w;
    float a  = __fmul_rn(m_lo, xt);
    float bq = __fmul_rn(m_lo, c_lo);
    float cc = __fmul_rn(m_up, xt);
    float d  = __fmul_rn(m_up, c_up);
    float A1 = __fsub_rn(__fadd_rn(a, bq), prev);
    float A2 = __fsub_rn(__fsub_rn(prev, cc), d);
    bool p1 = ((A1 > 0.0f) && (m_lo > 0.0f)) || ((A1 < 0.0f) && (m_lo < 0.0f));
    bool p2 = ((A2 > 0.0f) && (m_up > 0.0f)) || ((A2 < 0.0f) && (m_up < 0.0f));
    float t1 = p1 ? 0.0f : a;
    float t2 = p1 ? 0.0f : bq;
    float t3 = p2 ? 0.0f : cc;
    float t4 = p2 ? 0.0f : d;
    float t5 = (p1 && p2) ? prev : 0.0f;
    return __fadd_rn(__fadd_rn(__fadd_rn(__fadd_rn(t1, t2), t3), t4), t5);
}

__device__ __forceinline__ void cp16(uint32_t dst, const float4* src) {
    asm volatile("cp.async.cg.shared.global [%0], [%1], 16;" :: "r"(dst), "l"(src));
}

__device__ __forceinline__ void stcs16(float4* p, float4 v) {
    asm volatile("st.global.cs.v4.f32 [%0], {%1, %2, %3, %4};"
                 :: "l"(p), "f"(v.x), "f"(v.y), "f"(v.z), "f"(v.w) : "memory");
}

// Warp-scope coalesced cp.async copies for stage s (5 KB: 32 streams).
// Chunk-0 out-of-range warm loads (tb < 0) are skipped: that compute is
// discarded at s == WARMS-1 when lane my_c==0 substitutes out_prev.
__device__ __forceinline__ void issue_stage_w(const float* __restrict__ x,
                                              const float* __restrict__ w,
                                              int seq0, int s, uint32_t sb32, int lane) {
    // w: 8 passes x (4 streams x 8 lanes -> 4 full 128B segments / instr)
    #pragma unroll
    for (int p = 0; p < 8; p++) {
        int st = p * 4 + (lane >> 3);
        int j  = lane & 7;
        int sb = seq0 + (st >> 4);
        int sc = st & 15;
        int tb = sc * LCH - WARM + s * SS;
        if (tb >= 0)
            cp16(sb32 + (uint32_t)(st * STR + j) * 16,
                 (const float4*)w + (size_t)sb * TT + tb + j);
    }
    // x: 2 passes x (16 streams x lane-pairs -> full 32B sectors)
    #pragma unroll
    for (int p = 0; p < 2; p++) {
        int st = p * 16 + (lane >> 1);
        int k  = lane & 1;
        int sb = seq0 + (st >> 4);
        int sc = st & 15;
        int tb = sc * LCH - WARM + s * SS;
        if (tb >= 0)
            cp16(sb32 + (uint32_t)(st * STR + 8 + k) * 16,
                 (const float4*)(x + (size_t)sb * TT + tb) + k);
    }
    asm volatile("cp.async.commit_group;");
}

__global__ __launch_bounds__(TPB)
void backlash_fused(const float* __restrict__ x,
                    const float* __restrict__ w,
                    const float* __restrict__ out_prev,
                    float* __restrict__ out) {
    __shared__ float4 sB[NW][NBUF][32 * STR];   // 45056 B

    const int tid  = threadIdx.x;
    const int lane = tid & 31;
    const int wrp  = tid >> 5;
    const int seq0 = blockIdx.x * (2 * NW) + wrp * 2;   // 2 sequences per warp
    const int my_b = seq0 + (lane >> 4);
    const int my_c = lane & 15;

    const uint32_t b0 = (uint32_t)__cvta_generic_to_shared(&sB[wrp][0][0]);
    const uint32_t b1 = (uint32_t)__cvta_generic_to_shared(&sB[wrp][1][0]);

    const float op = (my_c == 0) ? out_prev[my_b] : 0.0f;
    float prev = 0.0f;
    float G = 0.0f;                 // state entering my chunk (post warm-up)

    issue_stage_w(x, w, seq0, 0, b0, lane);
    issue_stage_w(x, w, seq0, 1, b1, lane);

    #pragma unroll 1
    for (int s = 0; s < NST; s++) {
        if (s == NST - 1) { asm volatile("cp.async.wait_group 0;"); }
        else              { asm volatile("cp.async.wait_group 1;"); }
        __syncwarp();

        const uint32_t cb = (s & 1) ? b1 : b0;
        const float4* bp = &sB[wrp][s & 1][lane * STR];
        float4 x0 = bp[8];
        float4 x1 = bp[9];
        float o0, o1, o2, o3, o4, o5, o6, o7;
        prev = bl_step(prev, x0.x, bp[0]); o0 = prev;
        prev = bl_step(prev, x0.y, bp[1]); o1 = prev;
        prev = bl_step(prev, x0.z, bp[2]); o2 = prev;
        prev = bl_step(prev, x0.w, bp[3]); o3 = prev;
        prev = bl_step(prev, x1.x, bp[4]); o4 = prev;
        prev = bl_step(prev, x1.y, bp[5]); o5 = prev;
        prev = bl_step(prev, x1.z, bp[6]); o6 = prev;
        prev = bl_step(prev, x1.w, bp[7]); o7 = prev;

        const bool emit = (s >= WARMS);
        if (emit) {
            // outputs into the consumed x slots (conflict-free STS.128)
            float4* wp = &sB[wrp][s & 1][lane * STR];
            wp[8] = make_float4(o0, o1, o2, o3);
            wp[9] = make_float4(o4, o5, o6, o7);
        }
        if (s == WARMS - 1) {               // warm-up complete
            if (my_c == 0) prev = op;       // chunk 0: discard garbage, take true init
            G = prev;
        }
        __syncwarp();

        if (emit) {
            // coalesced float4 stores (lane pairs; full 32B sectors), evict-first
            #pragma unroll
            for (int p = 0; p < 2; p++) {
                int st = p * 16 + (lane >> 1);
                int k  = lane & 1;
                int sb = seq0 + (st >> 4);
                int sc = st & 15;
                float4 v = sB[wrp][s & 1][st * STR + 8 + k];
                stcs16(((float4*)out) + (size_t)sb * (TT / 4) + sc * (LCH / 4)
                                      + (s - WARMS) * (SS / 4) + k, v);
            }
        }
        if (s + 2 < NST) {
            // Cross-lane reads above must complete before refilling this buffer.
            __syncwarp();
            issue_stage_w(x, w, seq0, s + 2, cb, lane);   // (s+2)&1 == s&1
        }
    }

    // ---- warp-local validation + replay backstop (exactness guarantee) ----
    const unsigned full = 0xFFFFFFFFu;
    float E = prev;
    float Ep = __shfl_up_sync(full, E, 1);
    bool ok = (my_c == 0) || (Ep == G);
    if (__ballot_sync(full, ok) != full) {
        // Rare: speculative warm-up failed to merge somewhere in this warp.
        int base = lane & 16;
        float st = E;                       // valid on owner lanes (my_c==0)
        #pragma unroll 1
        for (int c = 1; c < CHUNKS; c++) {
            float g = __shfl_sync(full, G, base + c);
            float e = __shfl_sync(full, E, base + c);
            if (my_c == 0) {
                if (st == g) {
                    st = e;
                } else {
                    const float*  xb = x + (size_t)my_b * TT;
                    const float4* wb = (const float4*)w + (size_t)my_b * TT;
                    float*        ob = out + (size_t)my_b * TT;
                    for (int t = c * LCH; t < (c + 1) * LCH; t++) {
                        st = bl_step(st, xb[t], wb[t]);
                        ob[t] = st;
                    }
                }
            }
        }
    }
}

extern "C" void kernel_launch(void* const* d_in, const int* in_sizes, int n_in,
                              void* d_out, int out_size) {
    const float* x = nullptr;        // (B, T, 1)
    const float* out_prev = nullptr; // (B, 1, 1)
    const float* w = nullptr;        // (B, T, 4)
    for (int i = 0; i < n_in; i++) {
        if (in_sizes[i] == BB * TT)          x = (const float*)d_in[i];
        else if (in_sizes[i] == BB)          out_prev = (const float*)d_in[i];
        else if (in_sizes[i] == BB * TT * 4) w = (const float*)d_in[i];
    }
    float* out = (float*)d_out;

    backlash_fused<<<BB / (2 * NW), TPB>>>(x, w, out_prev, out);
}

// round 13
// speedup vs baseline: 1.3488x; 1.0037x over previous
#include <cuda_runtime.h>
#include <cuda_bf16.h>
#include <cstdint>

// Backlash scan, B=4096, T=2048. Warp-autonomous fused kernel, exact result:
//  - each warp owns 2 sequences (32 streams = 2 seq x 16 chunks), double-buffered
//    cp.async pipeline per warp; no __syncthreads anywhere
//  - 16-step speculative warm-up, 8 steps/stage, 18 stages; chunk-0 warm skipped
//  - warm-stage loads tagged L2 evict_last so the stage-16/17 re-reads of the
//    same lines (predecessor chunk's tail emits) hit L2 instead of DRAM
//  - evict-first output stores; warp-local shfl validation + replay backstop

#define BB 4096
#define TT 2048
#define CHUNKS 16
#define LCH 128
#define SS 8
#define WARMS 2
#define WARM (WARMS * SS)       // 16
#define NST (WARMS + LCH / SS)  // 18
#define TPB 128
#define NW (TPB / 32)
#define STR 11                  // float4/stream/stage: 8 w + 2 x + 1 pad
#define NBUF 2

// One backlash step, bit-identical to the reference fp32 expression.
// h-thresholds via sign tests (exact for nonzero m).
__device__ __forceinline__ float bl_step(float prev, float xt, float4 wv) {
    float m_lo = wv.x, m_up = wv.y, c_lo = wv.z, c_up = wv.w;
    float a  = __fmul_rn(m_lo, xt);
    float bq = __fmul_rn(m_lo, c_lo);
    float cc = __fmul_rn(m_up, xt);
    float d  = __fmul_rn(m_up, c_up);
    float A1 = __fsub_rn(__fadd_rn(a, bq), prev);
    float A2 = __fsub_rn(__fsub_rn(prev, cc), d);
    bool p1 = ((A1 > 0.0f) && (m_lo > 0.0f)) || ((A1 < 0.0f) && (m_lo < 0.0f));
    bool p2 = ((A2 > 0.0f) && (m_up > 0.0f)) || ((A2 < 0.0f) && (m_up < 0.0f));
    float t1 = p1 ? 0.0f : a;
    float t2 = p1 ? 0.0f : bq;
    float t3 = p2 ? 0.0f : cc;
    float t4 = p2 ? 0.0f : d;
    float t5 = (p1 && p2) ? prev : 0.0f;
    return __fadd_rn(__fadd_rn(__fadd_rn(__fadd_rn(t1, t2), t3), t4), t5);
}

__device__ __forceinline__ void cp16(uint32_t dst, const float4* src) {
    asm volatile("cp.async.cg.shared.global [%0], [%1], 16;" :: "r"(dst), "l"(src));
}

__device__ __forceinline__ void cp16_el(uint32_t dst, const float4* src, uint64_t pol) {
    asm volatile("cp.async.cg.shared.global.L2::cache_hint [%0], [%1], 16, %2;"
                 :: "r"(dst), "l"(src), "l"(pol));
}

__device__ __forceinline__ void stcs16(float4* p, float4 v) {
    asm volatile("st.global.cs.v4.f32 [%0], {%1, %2, %3, %4};"
                 :: "l"(p), "f"(v.x), "f"(v.y), "f"(v.z), "f"(v.w) : "memory");
}

// Warp-scope coalesced cp.async copies for stage s (5 KB: 32 streams).
// Chunk-0 out-of-range warm loads (tb < 0) are skipped.
// EL != 0: tag loads L2 evict_last (warm stages only — those exact lines are
// re-read at stages NST-2/NST-1 as the predecessor chunk's tail emit slices).
__device__ __forceinline__ void issue_stage_w(const float* __restrict__ x,
                                              const float* __restrict__ w,
                                              int seq0, int s, uint32_t sb32,
                                              int lane, uint64_t pol, int EL) {
    // w: 8 passes x (4 streams x 8 lanes -> 4 full 128B segments / instr)
    #pragma unroll
    for (int p = 0; p < 8; p++) {
        int st = p * 4 + (lane >> 3);
        int j  = lane & 7;
        int sb = seq0 + (st >> 4);
        int sc = st & 15;
        int tb = sc * LCH - WARM + s * SS;
        if (tb >= 0) {
            const float4* src = (const float4*)w + (size_t)sb * TT + tb + j;
            uint32_t dst = sb32 + (uint32_t)(st * STR + j) * 16;
            if (EL) cp16_el(dst, src, pol); else cp16(dst, src);
        }
    }
    // x: 2 passes x (16 streams x lane-pairs -> full 32B sectors)
    #pragma unroll
    for (int p = 0; p < 2; p++) {
        int st = p * 16 + (lane >> 1);
        int k  = lane & 1;
        int sb = seq0 + (st >> 4);
        int sc = st & 15;
        int tb = sc * LCH - WARM + s * SS;
        if (tb >= 0) {
            const float4* src = (const float4*)(x + (size_t)sb * TT + tb) + k;
            uint32_t dst = sb32 + (uint32_t)(st * STR + 8 + k) * 16;
            if (EL) cp16_el(dst, src, pol); else cp16(dst, src);
        }
    }
    asm volatile("cp.async.commit_group;");
}

__global__ __launch_bounds__(TPB)
void backlash_fused(const float* __restrict__ x,
                    const float* __restrict__ w,
                    const float* __restrict__ out_prev,
                    float* __restrict__ out) {
    __shared__ float4 sB[NW][NBUF][32 * STR];   // 45056 B

    const int tid  = threadIdx.x;
    const int lane = tid & 31;
    const int wrp  = tid >> 5;
    const int seq0 = blockIdx.x * (2 * NW) + wrp * 2;   // 2 sequences per warp
    const int my_b = seq0 + (lane >> 4);
    const int my_c = lane & 15;

    const uint32_t b0 = (uint32_t)__cvta_generic_to_shared(&sB[wrp][0][0]);
    const uint32_t b1 = (uint32_t)__cvta_generic_to_shared(&sB[wrp][1][0]);

    uint64_t pol;
    asm("createpolicy.fractional.L2::evict_last.b64 %0, 1.0;" : "=l"(pol));

    const float op = (my_c == 0) ? out_prev[my_b] : 0.0f;
    float prev = 0.0f;
    float G = 0.0f;                 // state entering my chunk (post warm-up)

    // Warm stages: tag lines evict_last (they get re-read at stages 16/17).
    issue_stage_w(x, w, seq0, 0, b0, lane, pol, 1);
    issue_stage_w(x, w, seq0, 1, b1, lane, pol, 1);

    #pragma unroll 1
    for (int s = 0; s < NST; s++) {
        if (s == NST - 1) { asm volatile("cp.async.wait_group 0;"); }
        else              { asm volatile("cp.async.wait_group 1;"); }
        __syncwarp();

        const uint32_t cb = (s & 1) ? b1 : b0;
        const float4* bp = &sB[wrp][s & 1][lane * STR];
        float4 x0 = bp[8];
        float4 x1 = bp[9];
        float o0, o1, o2, o3, o4, o5, o6, o7;
        prev = bl_step(prev, x0.x, bp[0]); o0 = prev;
        prev = bl_step(prev, x0.y, bp[1]); o1 = prev;
        prev = bl_step(prev, x0.z, bp[2]); o2 = prev;
        prev = bl_step(prev, x0.w, bp[3]); o3 = prev;
        prev = bl_step(prev, x1.x, bp[4]); o4 = prev;
        prev = bl_step(prev, x1.y, bp[5]); o5 = prev;
        prev = bl_step(prev, x1.z, bp[6]); o6 = prev;
        prev = bl_step(prev, x1.w, bp[7]); o7 = prev;

        const bool emit = (s >= WARMS);
        if (emit) {
            // outputs into the consumed x slots (conflict-free STS.128)
            float4* wp = &sB[wrp][s & 1][lane * STR];
            wp[8] = make_float4(o0, o1, o2, o3);
            wp[9] = make_float4(o4, o5, o6, o7);
        }
        if (s == WARMS - 1) {               // warm-up complete
            if (my_c == 0) prev = op;       // chunk 0: discard garbage, take true init
            G = prev;
        }
        __syncwarp();

        if (emit) {
            // coalesced float4 stores (lane pairs; full 32B sectors), evict-first
            #pragma unroll
            for (int p = 0; p < 2; p++) {
                int st = p * 16 + (lane >> 1);
                int k  = lane & 1;
                int sb = seq0 + (st >> 4);
                int sc = st & 15;
                float4 v = sB[wrp][s & 1][st * STR + 8 + k];
                stcs16(((float4*)out) + (size_t)sb * (TT / 4) + sc * (LCH / 4)
                                      + (s - WARMS) * (SS / 4) + k, v);
            }
        }
        if (s + 2 < NST) {
            // Cross-lane reads above must complete before refilling this buffer.
            __syncwarp();
            issue_stage_w(x, w, seq0, s + 2, cb, lane, pol, 0);
        }
    }

    // ---- warp-local validation + replay backstop (exactness guarantee) ----
    const unsigned full = 0xFFFFFFFFu;
    float E = prev;
    float Ep = __shfl_up_sync(full, E, 1);
    bool ok = (my_c == 0) || (Ep == G);
    if (__ballot_sync(full, ok) != full) {
        // Rare: speculative warm-up failed to merge somewhere in this warp.
        int base = lane & 16;
        float st = E;                       // valid on owner lanes (my_c==0)
        #pragma unroll 1
        for (int c = 1; c < CHUNKS; c++) {
            float g = __shfl_sync(full, G, base + c);
            float e = __shfl_sync(full, E, base + c);
            if (my_c == 0) {
                if (st == g) {
                    st = e;
                } else {
                    const float*  xb = x + (size_t)my_b * TT;
                    const float4* wb = (const float4*)w + (size_t)my_b * TT;
                    float*        ob = out + (size_t)my_b * TT;
                    for (int t = c * LCH; t < (c + 1) * LCH; t++) {
                        st = bl_step(st, xb[t], wb[t]);
                        ob[t] = st;
                    }
                }
            }
        }
    }
}

extern "C" void kernel_launch(void* const* d_in, const int* in_sizes, int n_in,
                              void* d_out, int out_size) {
    const float* x = nullptr;        // (B, T, 1)
    const float* out_prev = nullptr; // (B, 1, 1)
    const float* w = nullptr;        // (B, T, 4)
    for (int i = 0; i < n_in; i++) {
        if (in_sizes[i] == BB * TT)          x = (const float*)d_in[i];
        else if (in_sizes[i] == BB)          out_prev = (const float*)d_in[i];
        else if (in_sizes[i] == BB * TT * 4) w = (const float*)d_in[i];
    }
    float* out = (float*)d_out;

    backlash_fused<<<BB / (2 * NW), TPB>>>(x, w, out_prev, out);
}

// round 14
// speedup vs baseline: 1.4163x; 1.0501x over previous
#include <cuda_runtime.h>
#include <cuda_bf16.h>
#include <cstdint>

// Backlash scan, B=4096, T=2048. Warp-autonomous fused kernel, exact result:
//  - each warp owns 2 sequences (32 streams = 2 seq x 16 chunks), double-buffered
//    cp.async pipeline per warp; no __syncthreads anywhere
//  - TPB=64 (2 warps/block) -> grid 1024: per-SM block-count imbalance 1.01
//    instead of 1.16 at grid 512 (this round's change)
//  - 16-step speculative warm-up, 8 steps/stage, 18 stages; chunk-0 warm skipped
//  - warm-stage loads tagged L2 evict_last (re-read at stages 16/17)
//  - evict-first output stores; warp-local shfl validation + replay backstop

#define BB 4096
#define TT 2048
#define CHUNKS 16
#define LCH 128
#define SS 8
#define WARMS 2
#define WARM (WARMS * SS)       // 16
#define NST (WARMS + LCH / SS)  // 18
#define TPB 64
#define NW (TPB / 32)
#define STR 11                  // float4/stream/stage: 8 w + 2 x + 1 pad
#define NBUF 2

// One backlash step, bit-identical to the reference fp32 expression.
// h-thresholds via sign tests (exact for nonzero m).
__device__ __forceinline__ float bl_step(float prev, float xt, float4 wv) {
    float m_lo = wv.x, m_up = wv.y, c_lo = wv.z, c_up = wv.w;
    float a  = __fmul_rn(m_lo, xt);
    float bq = __fmul_rn(m_lo, c_lo);
    float cc = __fmul_rn(m_up, xt);
    float d  = __fmul_rn(m_up, c_up);
    float A1 = __fsub_rn(__fadd_rn(a, bq), prev);
    float A2 = __fsub_rn(__fsub_rn(prev, cc), d);
    bool p1 = ((A1 > 0.0f) && (m_lo > 0.0f)) || ((A1 < 0.0f) && (m_lo < 0.0f));
    bool p2 = ((A2 > 0.0f) && (m_up > 0.0f)) || ((A2 < 0.0f) && (m_up < 0.0f));
    float t1 = p1 ? 0.0f : a;
    float t2 = p1 ? 0.0f : bq;
    float t3 = p2 ? 0.0f : cc;
    float t4 = p2 ? 0.0f : d;
    float t5 = (p1 && p2) ? prev : 0.0f;
    return __fadd_rn(__fadd_rn(__fadd_rn(__fadd_rn(t1, t2), t3), t4), t5);
}

__device__ __forceinline__ void cp16(uint32_t dst, const float4* src) {
    asm volatile("cp.async.cg.shared.global [%0], [%1], 16;" :: "r"(dst), "l"(src));
}

__device__ __forceinline__ void cp16_el(uint32_t dst, const float4* src, uint64_t pol) {
    asm volatile("cp.async.cg.shared.global.L2::cache_hint [%0], [%1], 16, %2;"
                 :: "r"(dst), "l"(src), "l"(pol));
}

__device__ __forceinline__ void stcs16(float4* p, float4 v) {
    asm volatile("st.global.cs.v4.f32 [%0], {%1, %2, %3, %4};"
                 :: "l"(p), "f"(v.x), "f"(v.y), "f"(v.z), "f"(v.w) : "memory");
}

// Warp-scope coalesced cp.async copies for stage s (5 KB: 32 streams).
// Chunk-0 out-of-range warm loads (tb < 0) are skipped.
// EL != 0: tag loads L2 evict_last (warm stages only).
__device__ __forceinline__ void issue_stage_w(const float* __restrict__ x,
                                              const float* __restrict__ w,
                                              int seq0, int s, uint32_t sb32,
                                              int lane, uint64_t pol, int EL) {
    // w: 8 passes x (4 streams x 8 lanes -> 4 full 128B segments / instr)
    #pragma unroll
    for (int p = 0; p < 8; p++) {
        int st = p * 4 + (lane >> 3);
        int j  = lane & 7;
        int sb = seq0 + (st >> 4);
        int sc = st & 15;
        int tb = sc * LCH - WARM + s * SS;
        if (tb >= 0) {
            const float4* src = (const float4*)w + (size_t)sb * TT + tb + j;
            uint32_t dst = sb32 + (uint32_t)(st * STR + j) * 16;
            if (EL) cp16_el(dst, src, pol); else cp16(dst, src);
        }
    }
    // x: 2 passes x (16 streams x lane-pairs -> full 32B sectors)
    #pragma unroll
    for (int p = 0; p < 2; p++) {
        int st = p * 16 + (lane >> 1);
        int k  = lane & 1;
        int sb = seq0 + (st >> 4);
        int sc = st & 15;
        int tb = sc * LCH - WARM + s * SS;
        if (tb >= 0) {
            const float4* src = (const float4*)(x + (size_t)sb * TT + tb) + k;
            uint32_t dst = sb32 + (uint32_t)(st * STR + 8 + k) * 16;
            if (EL) cp16_el(dst, src, pol); else cp16(dst, src);
        }
    }
    asm volatile("cp.async.commit_group;");
}

__global__ __launch_bounds__(TPB)
void backlash_fused(const float* __restrict__ x,
                    const float* __restrict__ w,
                    const float* __restrict__ out_prev,
                    float* __restrict__ out) {
    __shared__ float4 sB[NW][NBUF][32 * STR];   // 22528 B

    const int tid  = threadIdx.x;
    const int lane = tid & 31;
    const int wrp  = tid >> 5;
    const int seq0 = blockIdx.x * (2 * NW) + wrp * 2;   // 2 sequences per warp
    const int my_b = seq0 + (lane >> 4);
    const int my_c = lane & 15;

    const uint32_t b0 = (uint32_t)__cvta_generic_to_shared(&sB[wrp][0][0]);
    const uint32_t b1 = (uint32_t)__cvta_generic_to_shared(&sB[wrp][1][0]);

    uint64_t pol;
    asm("createpolicy.fractional.L2::evict_last.b64 %0, 1.0;" : "=l"(pol));

    const float op = (my_c == 0) ? out_prev[my_b] : 0.0f;
    float prev = 0.0f;
    float G = 0.0f;                 // state entering my chunk (post warm-up)

    // Warm stages: tag lines evict_last (they get re-read at stages 16/17).
    issue_stage_w(x, w, seq0, 0, b0, lane, pol, 1);
    issue_stage_w(x, w, seq0, 1, b1, lane, pol, 1);

    #pragma unroll 1
    for (int s = 0; s < NST; s++) {
        if (s == NST - 1) { asm volatile("cp.async.wait_group 0;"); }
        else              { asm volatile("cp.async.wait_group 1;"); }
        __syncwarp();

        const uint32_t cb = (s & 1) ? b1 : b0;
        const float4* bp = &sB[wrp][s & 1][lane * STR];
        float4 x0 = bp[8];
        float4 x1 = bp[9];
        float o0, o1, o2, o3, o4, o5, o6, o7;
        prev = bl_step(prev, x0.x, bp[0]); o0 = prev;
        prev = bl_step(prev, x0.y, bp[1]); o1 = prev;
        prev = bl_step(prev, x0.z, bp[2]); o2 = prev;
        prev = bl_step(prev, x0.w, bp[3]); o3 = prev;
        prev = bl_step(prev, x1.x, bp[4]); o4 = prev;
        prev = bl_step(prev, x1.y, bp[5]); o5 = prev;
        prev = bl_step(prev, x1.z, bp[6]); o6 = prev;
        prev = bl_step(prev, x1.w, bp[7]); o7 = prev;

        const bool emit = (s >= WARMS);
        if (emit) {
            // outputs into the consumed x slots (conflict-free STS.128)
            float4* wp = &sB[wrp][s & 1][lane * STR];
            wp[8] = make_float4(o0, o1, o2, o3);
            wp[9] = make_float4(o4, o5, o6, o7);
        }
        if (s == WARMS - 1) {               // warm-up complete
            if (my_c == 0) prev = op;       // chunk 0: discard garbage, take true init
            G = prev;
        }
        __syncwarp();

        if (emit) {
            // coalesced float4 stores (lane pairs; full 32B sectors), evict-first
            #pragma unroll
            for (int p = 0; p < 2; p++) {
                int st = p * 16 + (lane >> 1);
                int k  = lane & 1;
                int sb = seq0 + (st >> 4);
                int sc = st & 15;
                float4 v = sB[wrp][s & 1][st * STR + 8 + k];
                stcs16(((float4*)out) + (size_t)sb * (TT / 4) + sc * (LCH / 4)
                                      + (s - WARMS) * (SS / 4) + k, v);
            }
        }
        if (s + 2 < NST) {
            // Cross-lane reads above must complete before refilling this buffer.
            __syncwarp();
            issue_stage_w(x, w, seq0, s + 2, cb, lane, pol, 0);
        }
    }

    // ---- warp-local validation + replay backstop (exactness guarantee) ----
    const unsigned full = 0xFFFFFFFFu;
    float E = prev;
    float Ep = __shfl_up_sync(full, E, 1);
    bool ok = (my_c == 0) || (Ep == G);
    if (__ballot_sync(full, ok) != full) {
        // Rare: speculative warm-up failed to merge somewhere in this warp.
        int base = lane & 16;
        float st = E;                       // valid on owner lanes (my_c==0)
        #pragma unroll 1
        for (int c = 1; c < CHUNKS; c++) {
            float g = __shfl_sync(full, G, base + c);
            float e = __shfl_sync(full, E, base + c);
            if (my_c == 0) {
                if (st == g) {
                    st = e;
                } else {
                    const float*  xb = x + (size_t)my_b * TT;
                    const float4* wb = (const float4*)w + (size_t)my_b * TT;
                    float*        ob = out + (size_t)my_b * TT;
                    for (int t = c * LCH; t < (c + 1) * LCH; t++) {
                        st = bl_step(st, xb[t], wb[t]);
                        ob[t] = st;
                    }
                }
            }
        }
    }
}

extern "C" void kernel_launch(void* const* d_in, const int* in_sizes, int n_in,
                              void* d_out, int out_size) {
    const float* x = nullptr;        // (B, T, 1)
    const float* out_prev = nullptr; // (B, 1, 1)
    const float* w = nullptr;        // (B, T, 4)
    for (int i = 0; i < n_in; i++) {
        if (in_sizes[i] == BB * TT)          x = (const float*)d_in[i];
        else if (in_sizes[i] == BB)          out_prev = (const float*)d_in[i];
        else if (in_sizes[i] == BB * TT * 4) w = (const float*)d_in[i];
    }
    float* out = (float*)d_out;

    backlash_fused<<<BB / (2 * NW), TPB>>>(x, w, out_prev, out);
}